// round 10
// baseline (speedup 1.0000x reference)
#include <cuda_runtime.h>
#include <cuda_bf16.h>
#include <math_constants.h>
#include <cstdint>

#define LL 768
#define HH 8
#define EE 64
#define NH 32
#define DD 192
#define BQ 64
#define NTILE 12
#define NITEMS 384
#define GRID_ATTN 296
#define KSTR8 208           // padded int8 smem row stride for K (bytes)
#define VSTR 72             // bf16 elements per V^T smem row

// ---------------- scratch (device globals; no allocs) ----------------
// Q int8 2-term, FRAG-READY for m16n8k32: [nh][lt(12)][w(4)][c(6)][lane(32)][4B]
__device__ signed char g_Qfa[(size_t)NH * 12 * 4 * 6 * 512];
__device__ signed char g_Qfb[(size_t)NH * 12 * 4 * 6 * 512];
// K int8 2-term, row-major [nh][s][192]
__device__ signed char g_Ka[(size_t)NH * LL * DD];
__device__ signed char g_Kb[(size_t)NH * LL * DD];
// per-row scales (include /127): Q'row ~= a*(Qa + Qb/128)
__device__ float g_Qsc[(size_t)NH * LL];
__device__ float g_Ksc[(size_t)NH * LL];
// V^T bf16 hi/lo [nh][e][s]
__device__ __nv_bfloat16 g_Vhi[(size_t)NH * EE * LL];
__device__ __nv_bfloat16 g_Vlo[(size_t)NH * EE * LL];
__device__ unsigned int  g_ctr;

// ---------------- MMA helpers ----------------
__device__ __forceinline__ void mma_bf16(float* c, const uint32_t* a, uint32_t b0, uint32_t b1) {
    asm volatile("mma.sync.aligned.m16n8k16.row.col.f32.bf16.bf16.f32 "
                 "{%0,%1,%2,%3}, {%4,%5,%6,%7}, {%8,%9}, {%0,%1,%2,%3};"
                 : "+f"(c[0]), "+f"(c[1]), "+f"(c[2]), "+f"(c[3])
                 : "r"(a[0]), "r"(a[1]), "r"(a[2]), "r"(a[3]), "r"(b0), "r"(b1));
}
__device__ __forceinline__ void mma_s8(int* c, const uint32_t* a, uint32_t b0, uint32_t b1) {
    asm volatile("mma.sync.aligned.m16n8k32.row.col.s32.s8.s8.s32 "
                 "{%0,%1,%2,%3}, {%4,%5,%6,%7}, {%8,%9}, {%0,%1,%2,%3};"
                 : "+r"(c[0]), "+r"(c[1]), "+r"(c[2]), "+r"(c[3])
                 : "r"(a[0]), "r"(a[1]), "r"(a[2]), "r"(a[3]), "r"(b0), "r"(b1));
}

__device__ __forceinline__ uint32_t smem_u32(const void* p) {
    uint32_t a;
    asm("{ .reg .u64 t; cvta.to.shared.u64 t, %1; cvt.u32.u64 %0, t; }" : "=r"(a) : "l"(p));
    return a;
}

#define CP16(dst, src) asm volatile("cp.async.cg.shared.global [%0], [%1], 16;" :: "r"(dst), "l"(src))
#define CP_COMMIT()    asm volatile("cp.async.commit_group;" ::: "memory")
#define CP_WAIT1()     asm volatile("cp.async.wait_group 1;" ::: "memory")

__device__ __forceinline__ uint32_t pack_hi(float x, float y, uint32_t& lo) {
    __nv_bfloat162 h2;
    h2.x = __float2bfloat16(x);
    h2.y = __float2bfloat16(y);
    __nv_bfloat162 l2;
    l2.x = __float2bfloat16(x - __bfloat162float(h2.x));
    l2.y = __float2bfloat16(y - __bfloat162float(h2.y));
    lo = *(uint32_t*)&l2;
    return *(uint32_t*)&h2;
}

// 2-term int8 quantization of x (|x| <= 127): x ~= a + b/128
__device__ __forceinline__ char2 quant2(float x) {
    int ia = __float2int_rn(x);
    float r = x - (float)ia;
    int ib = __float2int_rn(r * 128.0f);
    return make_char2((signed char)ia, (signed char)ib);
}

// byte offset of element d (row rg in 16-row warp tile) inside the 3072-B frag block
__device__ __forceinline__ int foff(int d, int rg) {
    int c = d >> 5, k = d & 31;
    int lane = ((rg & 7) << 2) | ((k & 15) >> 2);
    int word = ((k >> 4) << 1) | (rg >> 3);
    return c * 512 + lane * 16 + word * 4 + (k & 3);
}

// ---------------------------------------------------------------------------
// prep (fused): blockIdx.x < 48 -> Q'/K' int8 quantized build; else V transpose.
// ---------------------------------------------------------------------------
__global__ void prep_kernel(const float* __restrict__ q, const float* __restrict__ k,
                            const float* __restrict__ values,
                            const float* __restrict__ freqs, const float* __restrict__ offsets,
                            const float* __restrict__ gains, const float* __restrict__ gate) {
    const int nh = blockIdx.y;
    const int n = nh >> 3, h = nh & 7;
    __shared__ float sred[8][8];          // [warp][0..3 qmax, 4..7 kmax]

    if (blockIdx.x < 48) {
        if (blockIdx.x == 0 && blockIdx.y == 0 && threadIdx.x == 0)
            g_ctr = GRID_ATTN;            // seed attn work queue

        int e  = threadIdx.x & 63;
        int j  = threadIdx.x >> 6;        // 0..3 -> rows l0..l0+3
        int l0 = blockIdx.x * 16 + j * 4;
        int he = h * 64 + e;

        float fr  = freqs[he];
        float f   = 0.5f / (1.0f + __expf(-fr));
        float off = offsets[he];
        float gn  = gains[he];
        float g   = (gn > 8.0f) ? gn : __logf(1.0f + __expf(gn));
        float gt  = gate[he];
        float c   = (1.0f - gt) * g * g;

        float lf    = (float)l0;
        float fl    = f * lf;
        float resid = fmaf(f, lf, -fl);
        float frac  = (fl - floorf(fl)) + resid;
        const float TWO_PI = 6.28318530717958647692f;
        float phk   = TWO_PI * frac;
        float argq  = phk + off;
        float cq = __cosf(argq), sq = __sinf(argq);
        float ck = __cosf(phk),  sk = __sinf(phk);
        float dph = TWO_PI * f;
        float cF = __cosf(dph), sF = __sinf(dph);

        float q0[4], q1[4], q2[4], k0[4], k1[4], k2[4], qmx[4], kmx[4];
        #pragma unroll
        for (int dl = 0; dl < 4; dl++) {
            int l = l0 + dl;
            size_t qi = ((size_t)(n * LL + l) * HH + h) * EE + e;
            float qv = q[qi] * 0.125f;    // softmax temp folded into Q'
            float kv = k[qi];
            q0[dl] = qv * gt;
            float qc = qv * c;
            q1[dl] = qc * cq; q2[dl] = qc * sq;
            k0[dl] = kv; k1[dl] = kv * ck; k2[dl] = kv * sk;
            qmx[dl] = fmaxf(fabsf(q0[dl]), fmaxf(fabsf(q1[dl]), fabsf(q2[dl])));
            kmx[dl] = fabsf(kv);
            float cq2 = cq * cF - sq * sF, sq2 = sq * cF + cq * sF;
            float ck2 = ck * cF - sk * sF, sk2 = sk * cF + ck * sF;
            cq = cq2; sq = sq2; ck = ck2; sk = sk2;
        }
        // warp reduce maxima
        #pragma unroll
        for (int o = 16; o >= 1; o >>= 1) {
            #pragma unroll
            for (int dl = 0; dl < 4; dl++) {
                qmx[dl] = fmaxf(qmx[dl], __shfl_xor_sync(0xffffffffu, qmx[dl], o));
                kmx[dl] = fmaxf(kmx[dl], __shfl_xor_sync(0xffffffffu, kmx[dl], o));
            }
        }
        int warp = threadIdx.x >> 5;
        if ((threadIdx.x & 31) == 0) {
            #pragma unroll
            for (int dl = 0; dl < 4; dl++) {
                sred[warp][dl]     = qmx[dl];
                sred[warp][4 + dl] = kmx[dl];
            }
        }
        __syncthreads();

        size_t kbase = (size_t)nh * LL * DD;
        #pragma unroll
        for (int dl = 0; dl < 4; dl++) {
            int l = l0 + dl;
            float qm = fmaxf(sred[2 * j][dl],     sred[2 * j + 1][dl]);
            float km = fmaxf(sred[2 * j][4 + dl], sred[2 * j + 1][4 + dl]);
            float aq = qm > 0.f ? 127.0f / qm : 0.f;
            float ak = km > 0.f ? 127.0f / km : 0.f;

            // ---- Q frag-ready ----
            int rg = l & 15, wq = (l >> 4) & 3, lt = l >> 6;
            size_t fb = (((size_t)(nh * 12 + lt) * 4 + wq) * 6) * 512;
            char2 qg = quant2(q0[dl] * aq);
            int og = foff(e, rg);
            g_Qfa[fb + og] = qg.x;
            g_Qfb[fb + og] = qg.y;
            char2 qc1 = quant2(q1[dl] * aq);
            char2 qc2 = quant2(q2[dl] * aq);
            int oc = foff(64 + 2 * e, rg);
            *(char2*)(g_Qfa + fb + oc) = make_char2(qc1.x, qc2.x);
            *(char2*)(g_Qfb + fb + oc) = make_char2(qc1.y, qc2.y);

            // ---- K row-major ----
            size_t kb = kbase + (size_t)l * DD;
            char2 kg = quant2(k0[dl] * ak);
            g_Ka[kb + e] = kg.x;
            g_Kb[kb + e] = kg.y;
            char2 kc1 = quant2(k1[dl] * ak);
            char2 kc2 = quant2(k2[dl] * ak);
            *(char2*)(g_Ka + kb + 64 + 2 * e) = make_char2(kc1.x, kc2.x);
            *(char2*)(g_Kb + kb + 64 + 2 * e) = make_char2(kc1.y, kc2.y);

            if (e == 0) {
                g_Qsc[(size_t)nh * LL + l] = qm * (1.0f / 127.0f);
                g_Ksc[(size_t)nh * LL + l] = km * (1.0f / 127.0f);
            }
        }
    } else {
        __shared__ float sm[64 * 65];
        int t = blockIdx.x - 48;
        int s0 = t * 64;

        #pragma unroll
        for (int i = 0; i < 16; i++) {
            int idx = threadIdx.x + i * 256;
            int r = idx >> 6, e = idx & 63;
            sm[e * 65 + r] = values[((size_t)(n * LL + s0 + r) * HH + h) * EE + e];
        }
        __syncthreads();

        #pragma unroll
        for (int i = 0; i < 8; i++) {
            int pid = threadIdx.x + i * 256;
            int e = pid >> 5, s2 = pid & 31;
            float v0 = sm[e * 65 + 2 * s2];
            float v1 = sm[e * 65 + 2 * s2 + 1];
            uint32_t lo;
            uint32_t hi = pack_hi(v0, v1, lo);
            size_t o = ((size_t)nh * EE + e) * LL + s0 + 2 * s2;
            *(uint32_t*)(g_Vhi + o) = hi;
            *(uint32_t*)(g_Vlo + o) = lo;
        }
    }
}

// ---------------------------------------------------------------------------
// attn: persistent flash attention. QK on int8 IMMA (2-term split, per-row
// scales), AV on bf16 HMMA (3-product). cp.async split commit groups.
// ---------------------------------------------------------------------------
__global__ __launch_bounds__(128, 2)
void attn_kernel(const float* __restrict__ mask, const float* __restrict__ keylen,
                 float* __restrict__ out) {
    extern __shared__ char sm8[];
    int8_t* sKa = (int8_t*)sm8;                              // [64][KSTR8]
    int8_t* sKb = sKa + 64 * KSTR8;
    __nv_bfloat16* sVhi = (__nv_bfloat16*)(sm8 + 2 * 64 * KSTR8);   // [64][VSTR]
    __nv_bfloat16* sVlo = sVhi + 64 * VSTR;
    float* sB = (float*)(sm8 + 2 * 64 * KSTR8 + 2 * 64 * VSTR * 2); // [64] K scales

    const int tid  = threadIdx.x;
    const int w    = tid >> 5;
    const int lane = tid & 31;
    const int g    = lane >> 2, t = lane & 3;

    const uint32_t bKa = smem_u32(sKa);
    const uint32_t bKb = smem_u32(sKb);
    const uint32_t bVhi = smem_u32(sVhi);
    const uint32_t bVlo = smem_u32(sVlo);
    const uint32_t bB  = smem_u32(sB);

    unsigned item = blockIdx.x;
    while (item < NITEMS) {
        const int nh = (int)(item / NTILE);
        const int lt = (int)(item % NTILE);
        const int nb = nh >> 3, h = nh & 7;
        const int l0 = lt * BQ;
        const int row0 = l0 + w * 16 + g;

        const int8_t* gKa = g_Ka + (size_t)nh * LL * DD;
        const int8_t* gKb = g_Kb + (size_t)nh * LL * DD;
        const float*  gKsc = g_Ksc + (size_t)nh * LL;
        const uint4*  qfa = (const uint4*)g_Qfa + ((size_t)(nh * 12 + lt) * 4 + w) * 192 + lane;
        const uint4*  qfb = (const uint4*)g_Qfb + ((size_t)(nh * 12 + lt) * 4 + w) * 192 + lane;
        const float arow0 = g_Qsc[(size_t)nh * LL + row0];
        const float arow1 = g_Qsc[(size_t)nh * LL + row0 + 8];

        auto issue_K = [&](int it2) {
            const int8_t* gA = gKa + (size_t)it2 * 64 * DD;
            const int8_t* gB = gKb + (size_t)it2 * 64 * DD;
            #pragma unroll
            for (int i = 0; i < 6; i++) {
                int idx = tid + i * 128;
                int r = idx / 12, c = idx % 12;
                uint32_t off = (uint32_t)(r * KSTR8 + c * 16);
                CP16(bKa + off, gA + r * DD + c * 16);
                CP16(bKb + off, gB + r * DD + c * 16);
            }
            if (tid < 16) CP16(bB + tid * 16, (const char*)(gKsc + it2 * 64) + tid * 16);
        };
        auto issue_V = [&](int it2) {
            #pragma unroll
            for (int i = 0; i < 4; i++) {
                int idx = tid + i * 128;
                int r = idx / 8, c = idx % 8;
                size_t go = ((size_t)nh * EE + r) * LL + it2 * 64 + c * 8;
                uint32_t off = (uint32_t)(r * VSTR + c * 8) * 2u;
                CP16(bVhi + off, (const uint4*)(g_Vhi + go));
                CP16(bVlo + off, (const uint4*)(g_Vlo + go));
            }
        };

        issue_K(0); CP_COMMIT();
        issue_V(0); CP_COMMIT();

        float O[8][4];
        #pragma unroll
        for (int n = 0; n < 8; n++)
            #pragma unroll
            for (int j2 = 0; j2 < 4; j2++) O[n][j2] = 0.f;
        float m0 = -CUDART_INF_F, m1 = -CUDART_INF_F, ls0 = 0.f, ls1 = 0.f;

        const float* mrow0b = mask + (size_t)row0 * LL;
        const float* mrow1b = mrow0b + 8 * LL;
        const float* klb    = keylen + (size_t)nb * LL;

        for (int it = 0; it < NTILE; it++) {
            CP_WAIT1();          // K(it)+scales ready (V(it) may be in flight)
            __syncthreads();

            // ---- S = Q' K'^T on IMMA: S1 = QaKa, S2 = QaKb + QbKa ----
            int S1[8][4], S2[8][4];
            #pragma unroll
            for (int n = 0; n < 8; n++)
                #pragma unroll
                for (int j2 = 0; j2 < 4; j2++) { S1[n][j2] = 0; S2[n][j2] = 0; }

            #pragma unroll
            for (int c = 0; c < 6; c++) {
                uint4 qa = qfa[c * 32];
                uint4 qb = qfb[c * 32];
                #pragma unroll
                for (int n = 0; n < 8; n++) {
                    const int8_t* ka = sKa + (n * 8 + g) * KSTR8 + c * 32 + 4 * t;
                    const int8_t* kb = sKb + (n * 8 + g) * KSTR8 + c * 32 + 4 * t;
                    uint32_t a0 = *(const uint32_t*)(ka);
                    uint32_t a1 = *(const uint32_t*)(ka + 16);
                    uint32_t b0 = *(const uint32_t*)(kb);
                    uint32_t b1 = *(const uint32_t*)(kb + 16);
                    mma_s8(S1[n], (const uint32_t*)&qa, a0, a1);
                    mma_s8(S2[n], (const uint32_t*)&qa, b0, b1);
                    mma_s8(S2[n], (const uint32_t*)&qb, a0, a1);
                }
            }

            // ---- dequantize: Sf = a_row * b_col * (S1 + S2/128) ----
            float Sf[8][4];
            #pragma unroll
            for (int n = 0; n < 8; n++) {
                float b0 = sB[n * 8 + 2 * t];
                float b1 = sB[n * 8 + 2 * t + 1];
                Sf[n][0] = ((float)S1[n][0] + (float)S2[n][0] * 0.0078125f) * (arow0 * b0);
                Sf[n][1] = ((float)S1[n][1] + (float)S2[n][1] * 0.0078125f) * (arow0 * b1);
                Sf[n][2] = ((float)S1[n][2] + (float)S2[n][2] * 0.0078125f) * (arow1 * b0);
                Sf[n][3] = ((float)S1[n][3] + (float)S2[n][3] * 0.0078125f) * (arow1 * b1);
            }
            __syncthreads();     // done reading sKa/sKb/sB

            if (it + 1 < NTILE) issue_K(it + 1);
            CP_COMMIT();

            // ---- bias: 0.125 * (mask + keylen) ----
            {
                const float* mr0 = mrow0b + it * 64;
                const float* mr1 = mrow1b + it * 64;
                const float* kl  = klb + it * 64;
                #pragma unroll
                for (int n = 0; n < 8; n++) {
                    int sc = n * 8 + 2 * t;
                    float2 a0 = *(const float2*)(mr0 + sc);
                    float2 a1 = *(const float2*)(mr1 + sc);
                    float2 kk = *(const float2*)(kl + sc);
                    Sf[n][0] += 0.125f * (a0.x + kk.x);
                    Sf[n][1] += 0.125f * (a0.y + kk.y);
                    Sf[n][2] += 0.125f * (a1.x + kk.x);
                    Sf[n][3] += 0.125f * (a1.y + kk.y);
                }
            }

            // ---- online softmax (rows quad-local) ----
            float mx0 = Sf[0][0], mx1 = Sf[0][2];
            #pragma unroll
            for (int n = 0; n < 8; n++) {
                mx0 = fmaxf(mx0, fmaxf(Sf[n][0], Sf[n][1]));
                mx1 = fmaxf(mx1, fmaxf(Sf[n][2], Sf[n][3]));
            }
            mx0 = fmaxf(mx0, __shfl_xor_sync(0xffffffffu, mx0, 1));
            mx0 = fmaxf(mx0, __shfl_xor_sync(0xffffffffu, mx0, 2));
            mx1 = fmaxf(mx1, __shfl_xor_sync(0xffffffffu, mx1, 1));
            mx1 = fmaxf(mx1, __shfl_xor_sync(0xffffffffu, mx1, 2));
            float m0n = fmaxf(m0, mx0), m1n = fmaxf(m1, mx1);
            float c0 = __expf(m0 - m0n), c1 = __expf(m1 - m1n);
            m0 = m0n; m1 = m1n;
            float s0 = 0.f, s1 = 0.f;
            #pragma unroll
            for (int n = 0; n < 8; n++) {
                Sf[n][0] = __expf(Sf[n][0] - m0n);
                Sf[n][1] = __expf(Sf[n][1] - m0n);
                Sf[n][2] = __expf(Sf[n][2] - m1n);
                Sf[n][3] = __expf(Sf[n][3] - m1n);
                s0 += Sf[n][0] + Sf[n][1];
                s1 += Sf[n][2] + Sf[n][3];
                O[n][0] *= c0; O[n][1] *= c0;
                O[n][2] *= c1; O[n][3] *= c1;
            }
            s0 += __shfl_xor_sync(0xffffffffu, s0, 1);
            s0 += __shfl_xor_sync(0xffffffffu, s0, 2);
            s1 += __shfl_xor_sync(0xffffffffu, s1, 1);
            s1 += __shfl_xor_sync(0xffffffffu, s1, 2);
            ls0 = ls0 * c0 + s0;
            ls1 = ls1 * c1 + s1;

            CP_WAIT1();          // V(it) ready (K(it+1) may be in flight)
            __syncthreads();

            // ---- O += P V : bf16 3-product (unchanged, proven precision) ----
            #pragma unroll
            for (int kc = 0; kc < 4; kc++) {
                uint32_t ph4[4], pl4[4];
                ph4[0] = pack_hi(Sf[2*kc][0],   Sf[2*kc][1],   pl4[0]);
                ph4[1] = pack_hi(Sf[2*kc][2],   Sf[2*kc][3],   pl4[1]);
                ph4[2] = pack_hi(Sf[2*kc+1][0], Sf[2*kc+1][1], pl4[2]);
                ph4[3] = pack_hi(Sf[2*kc+1][2], Sf[2*kc+1][3], pl4[3]);
                #pragma unroll
                for (int n = 0; n < 8; n++) {
                    const __nv_bfloat16* vhp = sVhi + (n * 8 + g) * VSTR + 2 * t + kc * 16;
                    const __nv_bfloat16* vlp = sVlo + (n * 8 + g) * VSTR + 2 * t + kc * 16;
                    uint32_t vh0 = *(const uint32_t*)(vhp);
                    uint32_t vh1 = *(const uint32_t*)(vhp + 8);
                    uint32_t vl0 = *(const uint32_t*)(vlp);
                    uint32_t vl1 = *(const uint32_t*)(vlp + 8);
                    mma_bf16(O[n], ph4, vh0, vh1);
                    mma_bf16(O[n], ph4, vl0, vl1);
                    mma_bf16(O[n], pl4, vh0, vh1);
                }
            }
            __syncthreads();     // done reading V smem

            if (it + 1 < NTILE) issue_V(it + 1);
            CP_COMMIT();
        }

        // ---- epilogue for this item ----
        float inv0 = 1.0f / ls0, inv1 = 1.0f / ls1;
        float* o0 = out + ((size_t)(nb * LL + row0) * HH + h) * EE;
        float* o1 = o0 + 8 * HH * EE;
        #pragma unroll
        for (int n = 0; n < 8; n++) {
            int e = n * 8 + 2 * t;
            *(float2*)(o0 + e) = make_float2(O[n][0] * inv0, O[n][1] * inv0);
            *(float2*)(o1 + e) = make_float2(O[n][2] * inv1, O[n][3] * inv1);
        }

        // ---- next work item ----
        __shared__ unsigned s_item;
        __syncthreads();
        if (tid == 0) s_item = atomicAdd(&g_ctr, 1u);
        __syncthreads();
        item = s_item;
    }
}

// ---------------------------------------------------------------------------
extern "C" void kernel_launch(void* const* d_in, const int* in_sizes, int n_in,
                              void* d_out, int out_size) {
    const float* queries = (const float*)d_in[0];
    const float* keys    = (const float*)d_in[1];
    const float* values  = (const float*)d_in[2];
    const float* mask    = (const float*)d_in[3];
    const float* keylen  = (const float*)d_in[4];
    const float* freqs   = (const float*)d_in[5];
    const float* offsets = (const float*)d_in[6];
    const float* gains   = (const float*)d_in[7];
    const float* gate    = (const float*)d_in[8];
    float* out = (float*)d_out;

    prep_kernel<<<dim3(48 + NTILE, NH), 256>>>(queries, keys, values,
                                               freqs, offsets, gains, gate);

    const int smem = 2 * 64 * KSTR8 + 2 * 64 * VSTR * 2 + 256;   // 45312 B
    cudaFuncSetAttribute(attn_kernel, cudaFuncAttributeMaxDynamicSharedMemorySize, smem);
    attn_kernel<<<GRID_ATTN, 128, smem>>>(mask, keylen, out);
}

// round 11
// speedup vs baseline: 1.8842x; 1.8842x over previous
#include <cuda_runtime.h>
#include <cuda_bf16.h>
#include <math_constants.h>
#include <cstdint>

#define LL 768
#define HH 8
#define EE 64
#define NH 32
#define DD 192
#define BQ 64
#define NTILE 12
#define NITEMS 384          // 12 l-tiles x 32 nh
#define GRID_ATTN 296       // exactly 2 CTAs/SM on 148 SMs
#define KSTR 200            // padded smem row stride (bf16)
#define VSTR 72

// ---------------- scratch (device globals; no allocs) ----------------
// d-layout: d = e for gate channel (0..63); d = 64+2e (cos), 65+2e (sin).
__device__ __nv_bfloat16 g_Qhi[(size_t)NH * LL * DD];
__device__ __nv_bfloat16 g_Qlo[(size_t)NH * LL * DD];
__device__ __nv_bfloat16 g_Khi[(size_t)NH * LL * DD];
__device__ __nv_bfloat16 g_Klo[(size_t)NH * LL * DD];
__device__ __nv_bfloat16 g_Vhi[(size_t)NH * EE * LL];   // transposed [nh][e][s]
__device__ __nv_bfloat16 g_Vlo[(size_t)NH * EE * LL];
__device__ unsigned int  g_ctr;

// m16n8k16 row.col bf16 MMA, f32 accumulate
__device__ __forceinline__ void mma_bf16(float* c, const uint32_t* a, uint32_t b0, uint32_t b1) {
    asm volatile("mma.sync.aligned.m16n8k16.row.col.f32.bf16.bf16.f32 "
                 "{%0,%1,%2,%3}, {%4,%5,%6,%7}, {%8,%9}, {%0,%1,%2,%3};"
                 : "+f"(c[0]), "+f"(c[1]), "+f"(c[2]), "+f"(c[3])
                 : "r"(a[0]), "r"(a[1]), "r"(a[2]), "r"(a[3]), "r"(b0), "r"(b1));
}

__device__ __forceinline__ uint32_t smem_u32(const void* p) {
    uint32_t a;
    asm("{ .reg .u64 t; cvta.to.shared.u64 t, %1; cvt.u32.u64 %0, t; }" : "=r"(a) : "l"(p));
    return a;
}

#define CP16(dst, src) asm volatile("cp.async.cg.shared.global [%0], [%1], 16;" :: "r"(dst), "l"(src))
#define CP_COMMIT()    asm volatile("cp.async.commit_group;" ::: "memory")
#define CP_WAIT0()     asm volatile("cp.async.wait_group 0;" ::: "memory")

__device__ __forceinline__ uint32_t pack_hi(float x, float y, uint32_t& lo) {
    __nv_bfloat162 h2;
    h2.x = __float2bfloat16(x);
    h2.y = __float2bfloat16(y);
    __nv_bfloat162 l2;
    l2.x = __float2bfloat16(x - __bfloat162float(h2.x));
    l2.y = __float2bfloat16(y - __bfloat162float(h2.y));
    lo = *(uint32_t*)&l2;
    return *(uint32_t*)&h2;
}

// ---------------------------------------------------------------------------
// prep (fused): blockIdx.x < 48 -> Q'/K' build; else -> V transpose.
// ---------------------------------------------------------------------------
__global__ void prep_kernel(const float* __restrict__ q, const float* __restrict__ k,
                            const float* __restrict__ values,
                            const float* __restrict__ freqs, const float* __restrict__ offsets,
                            const float* __restrict__ gains, const float* __restrict__ gate) {
    const int nh = blockIdx.y;
    const int n = nh >> 3, h = nh & 7;

    if (blockIdx.x < 48) {
        if (blockIdx.x == 0 && blockIdx.y == 0 && threadIdx.x == 0)
            g_ctr = GRID_ATTN;                // seed attn work queue

        int e  = threadIdx.x & 63;
        int j  = threadIdx.x >> 6;            // 0..3
        int l0 = blockIdx.x * 16 + j * 4;
        int he = h * 64 + e;

        float fr  = freqs[he];
        float f   = 0.5f / (1.0f + __expf(-fr));
        float off = offsets[he];
        float gn  = gains[he];
        float g   = (gn > 8.0f) ? gn : __logf(1.0f + __expf(gn));
        float gt  = gate[he];
        float c   = (1.0f - gt) * g * g;

        float lf    = (float)l0;
        float fl    = f * lf;
        float resid = fmaf(f, lf, -fl);
        float frac  = (fl - floorf(fl)) + resid;
        const float TWO_PI = 6.28318530717958647692f;
        float phk   = TWO_PI * frac;
        float argq  = phk + off;
        float cq = __cosf(argq), sq = __sinf(argq);
        float ck = __cosf(phk),  sk = __sinf(phk);
        float dph = TWO_PI * f;
        float cF = __cosf(dph), sF = __sinf(dph);

        #pragma unroll
        for (int dl = 0; dl < 4; dl++) {
            int l = l0 + dl;
            size_t qi = ((size_t)(n * LL + l) * HH + h) * EE + e;
            float qv = q[qi] * 0.125f;        // softmax temp folded into Q'
            float kv = k[qi];

            size_t base = ((size_t)nh * LL + l) * DD;
            {
                float v = qv * gt;
                __nv_bfloat16 hi = __float2bfloat16(v);
                g_Qhi[base + e] = hi;
                g_Qlo[base + e] = __float2bfloat16(v - __bfloat162float(hi));
                __nv_bfloat16 whi = __float2bfloat16(kv);
                g_Khi[base + e] = whi;
                g_Klo[base + e] = __float2bfloat16(kv - __bfloat162float(whi));
            }
            {
                float qc = qv * c;
                float vx = qc * cq, vy = qc * sq;
                uint32_t lo;
                uint32_t hi = pack_hi(vx, vy, lo);
                *(uint32_t*)(g_Qhi + base + 64 + 2 * e) = hi;
                *(uint32_t*)(g_Qlo + base + 64 + 2 * e) = lo;
                float wx = kv * ck, wy = kv * sk;
                uint32_t wlo;
                uint32_t whi = pack_hi(wx, wy, wlo);
                *(uint32_t*)(g_Khi + base + 64 + 2 * e) = whi;
                *(uint32_t*)(g_Klo + base + 64 + 2 * e) = wlo;
            }
            float cq2 = cq * cF - sq * sF, sq2 = sq * cF + cq * sF;
            float ck2 = ck * cF - sk * sF, sk2 = sk * cF + ck * sF;
            cq = cq2; sq = sq2; ck = ck2; sk = sk2;
        }
    } else {
        __shared__ float sm[64 * 65];
        int t = blockIdx.x - 48;
        int s0 = t * 64;

        #pragma unroll
        for (int i = 0; i < 16; i++) {
            int idx = threadIdx.x + i * 256;
            int r = idx >> 6, e = idx & 63;
            sm[e * 65 + r] = values[((size_t)(n * LL + s0 + r) * HH + h) * EE + e];
        }
        __syncthreads();

        #pragma unroll
        for (int i = 0; i < 8; i++) {
            int pid = threadIdx.x + i * 256;
            int e = pid >> 5, s2 = pid & 31;
            float v0 = sm[e * 65 + 2 * s2];
            float v1 = sm[e * 65 + 2 * s2 + 1];
            uint32_t lo;
            uint32_t hi = pack_hi(v0, v1, lo);
            size_t o = ((size_t)nh * EE + e) * LL + s0 + 2 * s2;
            *(uint32_t*)(g_Vhi + o) = hi;
            *(uint32_t*)(g_Vlo + o) = lo;
        }
    }
}

// ---------------------------------------------------------------------------
// attn: persistent work-queue flash attention on HMMA (bf16 3-product),
// cp.async pipelined. Early queue pop (tile 10) + cross-item tile-0 prefetch
// (tile 11) keep the LSU busy across item boundaries.
// ---------------------------------------------------------------------------
__global__ __launch_bounds__(128)
void attn_kernel(const float* __restrict__ mask, const float* __restrict__ keylen,
                 float* __restrict__ out) {
    extern __shared__ __nv_bfloat16 smem[];
    __nv_bfloat16* sKhi = smem;                              // [64][KSTR]
    __nv_bfloat16* sKlo = smem + 64 * KSTR;
    __nv_bfloat16* sVhi = smem + 2 * 64 * KSTR;              // [2][64][VSTR]
    __nv_bfloat16* sVlo = smem + 2 * 64 * KSTR + 2 * 64 * VSTR;
    __shared__ unsigned s_item;

    const int tid  = threadIdx.x;
    const int w    = tid >> 5;
    const int lane = tid & 31;
    const int g    = lane >> 2, t = lane & 3;

    const uint32_t bKhi = smem_u32(sKhi);
    const uint32_t bKlo = smem_u32(sKlo);
    const uint32_t bVhi = smem_u32(sVhi);
    const uint32_t bVlo = smem_u32(sVlo);

    // cooperative cp.async issue of tile it2 of item itm (K single buf, V buf vb)
    auto issue_tile = [&](unsigned itm, int it2, int vb) {
        const int nh2 = (int)(itm / NTILE);
        const uint4* gH = (const uint4*)(g_Khi + (size_t)nh2 * LL * DD) + (size_t)it2 * 64 * DD / 8;
        const uint4* gL = (const uint4*)(g_Klo + (size_t)nh2 * LL * DD) + (size_t)it2 * 64 * DD / 8;
        #pragma unroll
        for (int i = 0; i < 12; i++) {
            int idx = tid + i * 128;
            int r = idx / 24, c = idx % 24;
            uint32_t off = (uint32_t)(r * KSTR + c * 8) * 2u;
            CP16(bKhi + off, gH + idx);
            CP16(bKlo + off, gL + idx);
        }
        #pragma unroll
        for (int i = 0; i < 4; i++) {
            int idx = tid + i * 128;
            int r = idx / 8, c = idx % 8;
            size_t go = ((size_t)nh2 * EE + r) * LL + it2 * 64 + c * 8;
            uint32_t off = (uint32_t)(vb * 64 * VSTR + r * VSTR + c * 8) * 2u;
            CP16(bVhi + off, (const uint4*)(g_Vhi + go));
            CP16(bVlo + off, (const uint4*)(g_Vlo + go));
        }
    };

    unsigned item = blockIdx.x;
    if (item < NITEMS) {
        issue_tile(item, 0, 0);     // prologue prefetch for the first item only
        CP_COMMIT();
    }

    while (item < NITEMS) {
        const int nh = (int)(item / NTILE);
        const int lt = (int)(item % NTILE);
        const int nb = nh >> 3, h = nh & 7;
        const int l0 = lt * BQ;
        const int row0 = l0 + w * 16 + g;

        // ---- Q fragments (register resident for this item) ----
        uint32_t aQh[12][4], aQl[12][4];
        {
            const __nv_bfloat16* qh = g_Qhi + ((size_t)nh * LL + row0) * DD;
            const __nv_bfloat16* ql = g_Qlo + ((size_t)nh * LL + row0) * DD;
            #pragma unroll
            for (int c = 0; c < 12; c++) {
                int d0 = c * 16 + 2 * t;
                aQh[c][0] = *(const uint32_t*)(qh + d0);
                aQh[c][1] = *(const uint32_t*)(qh + 8 * DD + d0);
                aQh[c][2] = *(const uint32_t*)(qh + d0 + 8);
                aQh[c][3] = *(const uint32_t*)(qh + 8 * DD + d0 + 8);
                aQl[c][0] = *(const uint32_t*)(ql + d0);
                aQl[c][1] = *(const uint32_t*)(ql + 8 * DD + d0);
                aQl[c][2] = *(const uint32_t*)(ql + d0 + 8);
                aQl[c][3] = *(const uint32_t*)(ql + 8 * DD + d0 + 8);
            }
        }

        float O[8][4];
        #pragma unroll
        for (int n = 0; n < 8; n++)
            #pragma unroll
            for (int j = 0; j < 4; j++) O[n][j] = 0.f;
        float m0 = -CUDART_INF_F, m1 = -CUDART_INF_F, ls0 = 0.f, ls1 = 0.f;

        const float* mrow0b = mask + (size_t)row0 * LL;
        const float* mrow1b = mrow0b + 8 * LL;
        const float* klb    = keylen + (size_t)nb * LL;

        for (int it = 0; it < NTILE; it++) {
            CP_WAIT0();
            __syncthreads();

            // ---- S = Q' K'^T : 8 n-tiles x 12 k-chunks x 3 products ----
            float S[8][4];
            #pragma unroll
            for (int n = 0; n < 8; n++)
                #pragma unroll
                for (int j = 0; j < 4; j++) S[n][j] = 0.f;

            #pragma unroll
            for (int n = 0; n < 8; n++) {
                const __nv_bfloat16* kh = sKhi + (n * 8 + g) * KSTR + 2 * t;
                const __nv_bfloat16* kl = sKlo + (n * 8 + g) * KSTR + 2 * t;
                #pragma unroll
                for (int c = 0; c < 12; c++) {
                    uint32_t bh0 = *(const uint32_t*)(kh + c * 16);
                    uint32_t bh1 = *(const uint32_t*)(kh + c * 16 + 8);
                    uint32_t bl0 = *(const uint32_t*)(kl + c * 16);
                    uint32_t bl1 = *(const uint32_t*)(kl + c * 16 + 8);
                    mma_bf16(S[n], aQh[c], bh0, bh1);
                    mma_bf16(S[n], aQh[c], bl0, bl1);
                    mma_bf16(S[n], aQl[c], bh0, bh1);
                }
            }
            __syncthreads();   // all warps done reading K smem

            if (it == 10 && tid == 0)
                s_item = atomicAdd(&g_ctr, 1u);   // early pop (off critical path)

            if (it + 1 < NTILE) {
                issue_tile(item, it + 1, (it + 1) & 1);
            } else {
                unsigned nx = s_item;             // visible: written before tile-11 top sync
                if (nx < NITEMS) issue_tile(nx, 0, 0);   // V buf0 free at odd tile 11
            }
            CP_COMMIT();

            // ---- bias: 0.125 * (mask + keylen) ----
            {
                const float* mr0 = mrow0b + it * 64;
                const float* mr1 = mrow1b + it * 64;
                const float* kl  = klb + it * 64;
                #pragma unroll
                for (int n = 0; n < 8; n++) {
                    int sc = n * 8 + 2 * t;
                    float2 a0 = *(const float2*)(mr0 + sc);
                    float2 a1 = *(const float2*)(mr1 + sc);
                    float2 kk = *(const float2*)(kl + sc);
                    S[n][0] += 0.125f * (a0.x + kk.x);
                    S[n][1] += 0.125f * (a0.y + kk.y);
                    S[n][2] += 0.125f * (a1.x + kk.x);
                    S[n][3] += 0.125f * (a1.y + kk.y);
                }
            }

            // ---- online softmax (rows quad-local) ----
            float mx0 = S[0][0], mx1 = S[0][2];
            #pragma unroll
            for (int n = 0; n < 8; n++) {
                mx0 = fmaxf(mx0, fmaxf(S[n][0], S[n][1]));
                mx1 = fmaxf(mx1, fmaxf(S[n][2], S[n][3]));
            }
            mx0 = fmaxf(mx0, __shfl_xor_sync(0xffffffffu, mx0, 1));
            mx0 = fmaxf(mx0, __shfl_xor_sync(0xffffffffu, mx0, 2));
            mx1 = fmaxf(mx1, __shfl_xor_sync(0xffffffffu, mx1, 1));
            mx1 = fmaxf(mx1, __shfl_xor_sync(0xffffffffu, mx1, 2));
            float m0n = fmaxf(m0, mx0), m1n = fmaxf(m1, mx1);
            float c0 = __expf(m0 - m0n), c1 = __expf(m1 - m1n);
            m0 = m0n; m1 = m1n;
            float s0 = 0.f, s1 = 0.f;
            #pragma unroll
            for (int n = 0; n < 8; n++) {
                S[n][0] = __expf(S[n][0] - m0n);
                S[n][1] = __expf(S[n][1] - m0n);
                S[n][2] = __expf(S[n][2] - m1n);
                S[n][3] = __expf(S[n][3] - m1n);
                s0 += S[n][0] + S[n][1];
                s1 += S[n][2] + S[n][3];
                O[n][0] *= c0; O[n][1] *= c0;
                O[n][2] *= c1; O[n][3] *= c1;
            }
            s0 += __shfl_xor_sync(0xffffffffu, s0, 1);
            s0 += __shfl_xor_sync(0xffffffffu, s0, 2);
            s1 += __shfl_xor_sync(0xffffffffu, s1, 1);
            s1 += __shfl_xor_sync(0xffffffffu, s1, 2);
            ls0 = ls0 * c0 + s0;
            ls1 = ls1 * c1 + s1;

            // ---- P -> bf16 hi/lo A-fragments (in-register) ----
            uint32_t ph[4][4], pl[4][4];
            #pragma unroll
            for (int kc = 0; kc < 4; kc++) {
                ph[kc][0] = pack_hi(S[2*kc][0],   S[2*kc][1],   pl[kc][0]);
                ph[kc][1] = pack_hi(S[2*kc][2],   S[2*kc][3],   pl[kc][1]);
                ph[kc][2] = pack_hi(S[2*kc+1][0], S[2*kc+1][1], pl[kc][2]);
                ph[kc][3] = pack_hi(S[2*kc+1][2], S[2*kc+1][3], pl[kc][3]);
            }

            // ---- O += P V : 8 e-tiles x 4 s-chunks x 3 products ----
            const __nv_bfloat16* vbH = sVhi + (it & 1) * 64 * VSTR;
            const __nv_bfloat16* vbL = sVlo + (it & 1) * 64 * VSTR;
            #pragma unroll
            for (int n = 0; n < 8; n++) {
                const __nv_bfloat16* vh = vbH + (n * 8 + g) * VSTR + 2 * t;
                const __nv_bfloat16* vl = vbL + (n * 8 + g) * VSTR + 2 * t;
                #pragma unroll
                for (int kc = 0; kc < 4; kc++) {
                    uint32_t bh0 = *(const uint32_t*)(vh + kc * 16);
                    uint32_t bh1 = *(const uint32_t*)(vh + kc * 16 + 8);
                    uint32_t bl0 = *(const uint32_t*)(vl + kc * 16);
                    uint32_t bl1 = *(const uint32_t*)(vl + kc * 16 + 8);
                    mma_bf16(O[n], ph[kc], bh0, bh1);
                    mma_bf16(O[n], ph[kc], bl0, bl1);
                    mma_bf16(O[n], pl[kc], bh0, bh1);
                }
            }
        }

        // ---- epilogue for this item ----
        float inv0 = 1.0f / ls0, inv1 = 1.0f / ls1;
        float* o0 = out + ((size_t)(nb * LL + row0) * HH + h) * EE;
        float* o1 = o0 + 8 * HH * EE;
        #pragma unroll
        for (int n = 0; n < 8; n++) {
            int e = n * 8 + 2 * t;
            *(float2*)(o0 + e) = make_float2(O[n][0] * inv0, O[n][1] * inv0);
            *(float2*)(o1 + e) = make_float2(O[n][2] * inv1, O[n][3] * inv1);
        }

        item = s_item;   // popped at tile 10; synced at tile 11 top
    }
}

// ---------------------------------------------------------------------------
extern "C" void kernel_launch(void* const* d_in, const int* in_sizes, int n_in,
                              void* d_out, int out_size) {
    const float* queries = (const float*)d_in[0];
    const float* keys    = (const float*)d_in[1];
    const float* values  = (const float*)d_in[2];
    const float* mask    = (const float*)d_in[3];
    const float* keylen  = (const float*)d_in[4];
    const float* freqs   = (const float*)d_in[5];
    const float* offsets = (const float*)d_in[6];
    const float* gains   = (const float*)d_in[7];
    const float* gate    = (const float*)d_in[8];
    float* out = (float*)d_out;

    prep_kernel<<<dim3(48 + NTILE, NH), 256>>>(queries, keys, values,
                                               freqs, offsets, gains, gate);

    const int smem = (2 * 64 * KSTR + 4 * 64 * VSTR) * 2;   // 88064 B -> 2 CTAs/SM
    cudaFuncSetAttribute(attn_kernel, cudaFuncAttributeMaxDynamicSharedMemorySize, smem);
    attn_kernel<<<GRID_ATTN, 128, smem>>>(mask, keylen, out);
}

// round 12
// speedup vs baseline: 2.3810x; 1.2637x over previous
#include <cuda_runtime.h>
#include <cuda_bf16.h>
#include <cuda_fp16.h>
#include <math_constants.h>
#include <cstdint>

#define LL 768
#define HH 8
#define EE 64
#define NH 32
#define DD 192
#define BQ 64
#define NTILE 12
#define NITEMS 384          // 12 l-tiles x 32 nh
#define GRID_ATTN 304
#define KSTR 200            // padded smem row stride (bf16)
#define VSTR 72             // fp16 elements per V^T smem row

// ---------------- scratch (device globals; no allocs) ----------------
// d-layout: d = e for gate channel (0..63); d = 64+2e (cos), 65+2e (sin).
__device__ __nv_bfloat16 g_Qhi[(size_t)NH * LL * DD];
__device__ __nv_bfloat16 g_Qlo[(size_t)NH * LL * DD];
__device__ __nv_bfloat16 g_Khi[(size_t)NH * LL * DD];
__device__ __nv_bfloat16 g_Klo[(size_t)NH * LL * DD];
__device__ __half        g_V[(size_t)NH * EE * LL];     // transposed [nh][e][s], fp16
__device__ unsigned int  g_ctr;

// m16n8k16 row.col bf16 MMA, f32 accumulate
__device__ __forceinline__ void mma_bf16(float* c, const uint32_t* a, uint32_t b0, uint32_t b1) {
    asm volatile("mma.sync.aligned.m16n8k16.row.col.f32.bf16.bf16.f32 "
                 "{%0,%1,%2,%3}, {%4,%5,%6,%7}, {%8,%9}, {%0,%1,%2,%3};"
                 : "+f"(c[0]), "+f"(c[1]), "+f"(c[2]), "+f"(c[3])
                 : "r"(a[0]), "r"(a[1]), "r"(a[2]), "r"(a[3]), "r"(b0), "r"(b1));
}
// m16n8k16 row.col fp16 MMA, f32 accumulate (AV path)
__device__ __forceinline__ void mma_f16(float* c, const uint32_t* a, uint32_t b0, uint32_t b1) {
    asm volatile("mma.sync.aligned.m16n8k16.row.col.f32.f16.f16.f32 "
                 "{%0,%1,%2,%3}, {%4,%5,%6,%7}, {%8,%9}, {%0,%1,%2,%3};"
                 : "+f"(c[0]), "+f"(c[1]), "+f"(c[2]), "+f"(c[3])
                 : "r"(a[0]), "r"(a[1]), "r"(a[2]), "r"(a[3]), "r"(b0), "r"(b1));
}

__device__ __forceinline__ uint32_t smem_u32(const void* p) {
    uint32_t a;
    asm("{ .reg .u64 t; cvta.to.shared.u64 t, %1; cvt.u32.u64 %0, t; }" : "=r"(a) : "l"(p));
    return a;
}

#define CP16(dst, src) asm volatile("cp.async.cg.shared.global [%0], [%1], 16;" :: "r"(dst), "l"(src))
#define CP_COMMIT()    asm volatile("cp.async.commit_group;" ::: "memory")
#define CP_WAIT0()     asm volatile("cp.async.wait_group 0;" ::: "memory")

__device__ __forceinline__ uint32_t pack_hi(float x, float y, uint32_t& lo) {
    __nv_bfloat162 h2;
    h2.x = __float2bfloat16(x);
    h2.y = __float2bfloat16(y);
    __nv_bfloat162 l2;
    l2.x = __float2bfloat16(x - __bfloat162float(h2.x));
    l2.y = __float2bfloat16(y - __bfloat162float(h2.y));
    lo = *(uint32_t*)&l2;
    return *(uint32_t*)&h2;
}
__device__ __forceinline__ uint32_t pack_h2(float x, float y) {
    __half2 h = __floats2half2_rn(x, y);
    return *(uint32_t*)&h;
}

// ---------------------------------------------------------------------------
// prep (fused): blockIdx.x < 48 -> Q'/K' build; else -> V transpose (fp16).
// ---------------------------------------------------------------------------
__global__ void prep_kernel(const float* __restrict__ q, const float* __restrict__ k,
                            const float* __restrict__ values,
                            const float* __restrict__ freqs, const float* __restrict__ offsets,
                            const float* __restrict__ gains, const float* __restrict__ gate) {
    const int nh = blockIdx.y;
    const int n = nh >> 3, h = nh & 7;

    if (blockIdx.x < 48) {
        if (blockIdx.x == 0 && blockIdx.y == 0 && threadIdx.x == 0)
            g_ctr = GRID_ATTN;                // seed attn work queue

        int e  = threadIdx.x & 63;
        int j  = threadIdx.x >> 6;            // 0..3
        int l0 = blockIdx.x * 16 + j * 4;
        int he = h * 64 + e;

        float fr  = freqs[he];
        float f   = 0.5f / (1.0f + __expf(-fr));
        float off = offsets[he];
        float gn  = gains[he];
        float g   = (gn > 8.0f) ? gn : __logf(1.0f + __expf(gn));
        float gt  = gate[he];
        float c   = (1.0f - gt) * g * g;

        float lf    = (float)l0;
        float fl    = f * lf;
        float resid = fmaf(f, lf, -fl);
        float frac  = (fl - floorf(fl)) + resid;
        const float TWO_PI = 6.28318530717958647692f;
        float phk   = TWO_PI * frac;
        float argq  = phk + off;
        float cq = __cosf(argq), sq = __sinf(argq);
        float ck = __cosf(phk),  sk = __sinf(phk);
        float dph = TWO_PI * f;
        float cF = __cosf(dph), sF = __sinf(dph);

        #pragma unroll
        for (int dl = 0; dl < 4; dl++) {
            int l = l0 + dl;
            size_t qi = ((size_t)(n * LL + l) * HH + h) * EE + e;
            float qv = q[qi] * 0.125f;        // softmax temp folded into Q'
            float kv = k[qi];

            size_t base = ((size_t)nh * LL + l) * DD;
            {
                float v = qv * gt;
                __nv_bfloat16 hi = __float2bfloat16(v);
                g_Qhi[base + e] = hi;
                g_Qlo[base + e] = __float2bfloat16(v - __bfloat162float(hi));
                __nv_bfloat16 whi = __float2bfloat16(kv);
                g_Khi[base + e] = whi;
                g_Klo[base + e] = __float2bfloat16(kv - __bfloat162float(whi));
            }
            {
                float qc = qv * c;
                float vx = qc * cq, vy = qc * sq;
                uint32_t lo;
                uint32_t hi = pack_hi(vx, vy, lo);
                *(uint32_t*)(g_Qhi + base + 64 + 2 * e) = hi;
                *(uint32_t*)(g_Qlo + base + 64 + 2 * e) = lo;
                float wx = kv * ck, wy = kv * sk;
                uint32_t wlo;
                uint32_t whi = pack_hi(wx, wy, wlo);
                *(uint32_t*)(g_Khi + base + 64 + 2 * e) = whi;
                *(uint32_t*)(g_Klo + base + 64 + 2 * e) = wlo;
            }
            float cq2 = cq * cF - sq * sF, sq2 = sq * cF + cq * sF;
            float ck2 = ck * cF - sk * sF, sk2 = sk * cF + ck * sF;
            cq = cq2; sq = sq2; ck = ck2; sk = sk2;
        }
    } else {
        __shared__ float sm[64 * 65];
        int t = blockIdx.x - 48;
        int s0 = t * 64;

        #pragma unroll
        for (int i = 0; i < 16; i++) {
            int idx = threadIdx.x + i * 256;
            int r = idx >> 6, e = idx & 63;
            sm[e * 65 + r] = values[((size_t)(n * LL + s0 + r) * HH + h) * EE + e];
        }
        __syncthreads();

        #pragma unroll
        for (int i = 0; i < 8; i++) {
            int pid = threadIdx.x + i * 256;
            int e = pid >> 5, s2 = pid & 31;
            float v0 = sm[e * 65 + 2 * s2];
            float v1 = sm[e * 65 + 2 * s2 + 1];
            size_t o = ((size_t)nh * EE + e) * LL + s0 + 2 * s2;
            *(uint32_t*)(g_V + o) = pack_h2(v0, v1);
        }
    }
}

// ---------------------------------------------------------------------------
// attn: persistent work-queue flash attention. QK: bf16 3-product HMMA
// (precision-critical). AV: single fp16 HMMA (P,V fp16; rel-err ~2e-4).
// cp.async pipelined exactly as the proven R8 structure.
// ---------------------------------------------------------------------------
__global__ __launch_bounds__(128)
void attn_kernel(const float* __restrict__ mask, const float* __restrict__ keylen,
                 float* __restrict__ out) {
    extern __shared__ __nv_bfloat16 smem[];
    __nv_bfloat16* sKhi = smem;                              // [64][KSTR]
    __nv_bfloat16* sKlo = smem + 64 * KSTR;
    __half* sV = (__half*)(smem + 2 * 64 * KSTR);            // [2][64][VSTR]

    const int tid  = threadIdx.x;
    const int w    = tid >> 5;
    const int lane = tid & 31;
    const int g    = lane >> 2, t = lane & 3;

    const uint32_t bKhi = smem_u32(sKhi);
    const uint32_t bKlo = smem_u32(sKlo);
    const uint32_t bV   = smem_u32(sV);

    unsigned item = blockIdx.x;
    while (item < NITEMS) {
        const int nh = (int)(item / NTILE);
        const int lt = (int)(item % NTILE);
        const int nb = nh >> 3, h = nh & 7;
        const int l0 = lt * BQ;
        const int row0 = l0 + w * 16 + g;

        const uint4* gKhiB = (const uint4*)(g_Khi + (size_t)nh * LL * DD);
        const uint4* gKloB = (const uint4*)(g_Klo + (size_t)nh * LL * DD);

        // issue cp.async group for tile it2 (K single buf, V buf vb)
        auto issue_tile = [&](int it2, int vb) {
            const uint4* gH = gKhiB + (size_t)it2 * 64 * DD / 8;
            const uint4* gL = gKloB + (size_t)it2 * 64 * DD / 8;
            #pragma unroll
            for (int i = 0; i < 12; i++) {
                int idx = tid + i * 128;
                int r = idx / 24, c = idx % 24;
                uint32_t off = (uint32_t)(r * KSTR + c * 8) * 2u;
                CP16(bKhi + off, gH + idx);
                CP16(bKlo + off, gL + idx);
            }
            #pragma unroll
            for (int i = 0; i < 4; i++) {
                int idx = tid + i * 128;
                int r = idx / 8, c = idx % 8;
                size_t go = ((size_t)nh * EE + r) * LL + it2 * 64 + c * 8;
                uint32_t off = (uint32_t)(vb * 64 * VSTR + r * VSTR + c * 8) * 2u;
                CP16(bV + off, (const uint4*)(g_V + go));
            }
        };

        issue_tile(0, 0);
        CP_COMMIT();

        // ---- Q fragments (register resident for this item) ----
        uint32_t aQh[12][4], aQl[12][4];
        {
            const __nv_bfloat16* qh = g_Qhi + ((size_t)nh * LL + row0) * DD;
            const __nv_bfloat16* ql = g_Qlo + ((size_t)nh * LL + row0) * DD;
            #pragma unroll
            for (int c = 0; c < 12; c++) {
                int d0 = c * 16 + 2 * t;
                aQh[c][0] = *(const uint32_t*)(qh + d0);
                aQh[c][1] = *(const uint32_t*)(qh + 8 * DD + d0);
                aQh[c][2] = *(const uint32_t*)(qh + d0 + 8);
                aQh[c][3] = *(const uint32_t*)(qh + 8 * DD + d0 + 8);
                aQl[c][0] = *(const uint32_t*)(ql + d0);
                aQl[c][1] = *(const uint32_t*)(ql + 8 * DD + d0);
                aQl[c][2] = *(const uint32_t*)(ql + d0 + 8);
                aQl[c][3] = *(const uint32_t*)(ql + 8 * DD + d0 + 8);
            }
        }

        float O[8][4];
        #pragma unroll
        for (int n = 0; n < 8; n++)
            #pragma unroll
            for (int j = 0; j < 4; j++) O[n][j] = 0.f;
        float m0 = -CUDART_INF_F, m1 = -CUDART_INF_F, ls0 = 0.f, ls1 = 0.f;

        const float* mrow0b = mask + (size_t)row0 * LL;
        const float* mrow1b = mrow0b + 8 * LL;
        const float* klb    = keylen + (size_t)nb * LL;

        for (int it = 0; it < NTILE; it++) {
            CP_WAIT0();
            __syncthreads();

            // ---- S = Q' K'^T : c outer, staged B frags, n-minor issue ----
            float S[8][4];
            #pragma unroll
            for (int n = 0; n < 8; n++)
                #pragma unroll
                for (int j = 0; j < 4; j++) S[n][j] = 0.f;

            #pragma unroll
            for (int c = 0; c < 12; c++) {
                uint32_t bh[8][2], bl[8][2];
                #pragma unroll
                for (int n = 0; n < 8; n++) {
                    const __nv_bfloat16* kh = sKhi + (n * 8 + g) * KSTR + 2 * t + c * 16;
                    const __nv_bfloat16* kl = sKlo + (n * 8 + g) * KSTR + 2 * t + c * 16;
                    bh[n][0] = *(const uint32_t*)(kh);
                    bh[n][1] = *(const uint32_t*)(kh + 8);
                    bl[n][0] = *(const uint32_t*)(kl);
                    bl[n][1] = *(const uint32_t*)(kl + 8);
                }
                #pragma unroll
                for (int n = 0; n < 8; n++) mma_bf16(S[n], aQh[c], bh[n][0], bh[n][1]);
                #pragma unroll
                for (int n = 0; n < 8; n++) mma_bf16(S[n], aQh[c], bl[n][0], bl[n][1]);
                #pragma unroll
                for (int n = 0; n < 8; n++) mma_bf16(S[n], aQl[c], bh[n][0], bh[n][1]);
            }
            __syncthreads();   // all warps done reading K smem

            if (it + 1 < NTILE) issue_tile(it + 1, (it + 1) & 1);
            CP_COMMIT();

            // ---- bias: 0.125 * (mask + keylen) ----
            {
                const float* mr0 = mrow0b + it * 64;
                const float* mr1 = mrow1b + it * 64;
                const float* kl  = klb + it * 64;
                #pragma unroll
                for (int n = 0; n < 8; n++) {
                    int sc = n * 8 + 2 * t;
                    float2 a0 = *(const float2*)(mr0 + sc);
                    float2 a1 = *(const float2*)(mr1 + sc);
                    float2 kk = *(const float2*)(kl + sc);
                    S[n][0] += 0.125f * (a0.x + kk.x);
                    S[n][1] += 0.125f * (a0.y + kk.y);
                    S[n][2] += 0.125f * (a1.x + kk.x);
                    S[n][3] += 0.125f * (a1.y + kk.y);
                }
            }

            // ---- online softmax (rows quad-local) ----
            float mx0 = S[0][0], mx1 = S[0][2];
            #pragma unroll
            for (int n = 0; n < 8; n++) {
                mx0 = fmaxf(mx0, fmaxf(S[n][0], S[n][1]));
                mx1 = fmaxf(mx1, fmaxf(S[n][2], S[n][3]));
            }
            mx0 = fmaxf(mx0, __shfl_xor_sync(0xffffffffu, mx0, 1));
            mx0 = fmaxf(mx0, __shfl_xor_sync(0xffffffffu, mx0, 2));
            mx1 = fmaxf(mx1, __shfl_xor_sync(0xffffffffu, mx1, 1));
            mx1 = fmaxf(mx1, __shfl_xor_sync(0xffffffffu, mx1, 2));
            float m0n = fmaxf(m0, mx0), m1n = fmaxf(m1, mx1);
            float c0 = __expf(m0 - m0n), c1 = __expf(m1 - m1n);
            m0 = m0n; m1 = m1n;
            float s0 = 0.f, s1 = 0.f;
            #pragma unroll
            for (int n = 0; n < 8; n++) {
                S[n][0] = __expf(S[n][0] - m0n);
                S[n][1] = __expf(S[n][1] - m0n);
                S[n][2] = __expf(S[n][2] - m1n);
                S[n][3] = __expf(S[n][3] - m1n);
                s0 += S[n][0] + S[n][1];
                s1 += S[n][2] + S[n][3];
                O[n][0] *= c0; O[n][1] *= c0;
                O[n][2] *= c1; O[n][3] *= c1;
            }
            s0 += __shfl_xor_sync(0xffffffffu, s0, 1);
            s0 += __shfl_xor_sync(0xffffffffu, s0, 2);
            s1 += __shfl_xor_sync(0xffffffffu, s1, 1);
            s1 += __shfl_xor_sync(0xffffffffu, s1, 2);
            ls0 = ls0 * c0 + s0;
            ls1 = ls1 * c1 + s1;

            // ---- P -> fp16 A-fragments (single product) ----
            uint32_t ph[4][4];
            #pragma unroll
            for (int kc = 0; kc < 4; kc++) {
                ph[kc][0] = pack_h2(S[2*kc][0],   S[2*kc][1]);
                ph[kc][1] = pack_h2(S[2*kc][2],   S[2*kc][3]);
                ph[kc][2] = pack_h2(S[2*kc+1][0], S[2*kc+1][1]);
                ph[kc][3] = pack_h2(S[2*kc+1][2], S[2*kc+1][3]);
            }

            // ---- O += P V : kc outer, staged V frags, single fp16 product ----
            const __half* vb = sV + (it & 1) * 64 * VSTR;
            #pragma unroll
            for (int kc = 0; kc < 4; kc++) {
                uint32_t vh[8][2];
                #pragma unroll
                for (int n = 0; n < 8; n++) {
                    const __half* vhp = vb + (n * 8 + g) * VSTR + 2 * t + kc * 16;
                    vh[n][0] = *(const uint32_t*)(vhp);
                    vh[n][1] = *(const uint32_t*)(vhp + 8);
                }
                #pragma unroll
                for (int n = 0; n < 8; n++) mma_f16(O[n], ph[kc], vh[n][0], vh[n][1]);
            }
        }

        // ---- epilogue for this item ----
        float inv0 = 1.0f / ls0, inv1 = 1.0f / ls1;
        float* o0 = out + ((size_t)(nb * LL + row0) * HH + h) * EE;
        float* o1 = o0 + 8 * HH * EE;
        #pragma unroll
        for (int n = 0; n < 8; n++) {
            int e = n * 8 + 2 * t;
            *(float2*)(o0 + e) = make_float2(O[n][0] * inv0, O[n][1] * inv0);
            *(float2*)(o1 + e) = make_float2(O[n][2] * inv1, O[n][3] * inv1);
        }

        // ---- next work item ----
        __shared__ unsigned s_item;
        __syncthreads();
        if (tid == 0) s_item = atomicAdd(&g_ctr, 1u);
        __syncthreads();
        item = s_item;
    }
}

// ---------------------------------------------------------------------------
extern "C" void kernel_launch(void* const* d_in, const int* in_sizes, int n_in,
                              void* d_out, int out_size) {
    const float* queries = (const float*)d_in[0];
    const float* keys    = (const float*)d_in[1];
    const float* values  = (const float*)d_in[2];
    const float* mask    = (const float*)d_in[3];
    const float* keylen  = (const float*)d_in[4];
    const float* freqs   = (const float*)d_in[5];
    const float* offsets = (const float*)d_in[6];
    const float* gains   = (const float*)d_in[7];
    const float* gate    = (const float*)d_in[8];
    float* out = (float*)d_out;

    prep_kernel<<<dim3(48 + NTILE, NH), 256>>>(queries, keys, values,
                                               freqs, offsets, gains, gate);

    const int smem = 2 * 64 * KSTR * 2 + 2 * 64 * VSTR * 2;   // 69632 B
    cudaFuncSetAttribute(attn_kernel, cudaFuncAttributeMaxDynamicSharedMemorySize, smem);
    attn_kernel<<<GRID_ATTN, 128, smem>>>(mask, keylen, out);
}